// round 6
// baseline (speedup 1.0000x reference)
#include <cuda_runtime.h>
#include <math.h>

// Problem constants (fixed shapes from reference)
#define NQ      262144      // total queries = B*L*cg = 4*1024*64
#define NSAM    1024        // prior samples
#define NPAIR   512         // sample pairs (f32x2 packing)
#define TSTRIDE 8           // floats per pair row in smem table (32 B rows: S only)
#define THREADS 512
#define QPT     2           // queries per thread
#define CHUNK   16          // pairs per argmax chunk
#define NCHUNK  (NPAIR / CHUNK)
#define ZHAT_OFF   0
#define NOQ_OFF    1048576  // B*L*C
#define IDX_OFF    2097152  // 2*B*L*C
#define FULL_OUT   2359296  // + B*L*cg

// ---- packed f32x2 helpers (Blackwell FFMA2/FMUL2) ----
__device__ __forceinline__ unsigned long long ffma2(unsigned long long a,
                                                    unsigned long long b,
                                                    unsigned long long c) {
    unsigned long long d;
    asm("fma.rn.f32x2 %0, %1, %2, %3;" : "=l"(d) : "l"(a), "l"(b), "l"(c));
    return d;
}
__device__ __forceinline__ unsigned long long fmul2(unsigned long long a,
                                                    unsigned long long b) {
    unsigned long long d;
    asm("mul.rn.f32x2 %0, %1, %2;" : "=l"(d) : "l"(a), "l"(b));
    return d;
}
__device__ __forceinline__ unsigned long long pack2(float x) {
    unsigned long long r;
    asm("mov.b64 %0, {%1, %1};" : "=l"(r) : "f"(x));
    return r;
}
__device__ __forceinline__ float lo2(unsigned long long a) {
    return __uint_as_float((unsigned)(a & 0xffffffffull));
}
__device__ __forceinline__ float hi2(unsigned long long a) {
    return __uint_as_float((unsigned)(a >> 32));
}

// Factored score for one query against one sample pair:
//   acc = sum_g S_g * (u_g + vh_g * S_g)
// Both main loop and rescan use this exact sequence -> bit-identical results.
__device__ __forceinline__ unsigned long long score_pair(
        const unsigned long long* uu, const unsigned long long* vh,
        unsigned long long s0, unsigned long long s1,
        unsigned long long s2, unsigned long long s3) {
    unsigned long long t, a;
    t = ffma2(vh[0], s0, uu[0]);  a = fmul2(s0, t);
    t = ffma2(vh[1], s1, uu[1]);  a = ffma2(s1, t, a);
    t = ffma2(vh[2], s2, uu[2]);  a = ffma2(s2, t, a);
    t = ffma2(vh[3], s3, uu[3]);  a = ffma2(s3, t, a);
    return a;
}

// Recompute one chunk's scores for one query; return smallest global sample
// index whose score equals target exactly (lo lane checked before hi lane).
__device__ __forceinline__ int rescan_chunk(const float* __restrict__ tab,
                                            const unsigned long long* uu,
                                            const unsigned long long* vh,
                                            int chunk, float target) {
    int found = NSAM;    // min-reduce => first match
    #pragma unroll 4
    for (int t = 0; t < CHUNK; t++) {
        int p = chunk * CHUNK + t;
        const float* base = &tab[p * TSTRIDE];
        ulonglong2 wa = *reinterpret_cast<const ulonglong2*>(base + 0);   // S0,S1
        ulonglong2 wb = *reinterpret_cast<const ulonglong2*>(base + 4);   // S2,S3
        unsigned long long a = score_pair(uu, vh, wa.x, wa.y, wb.x, wb.y);
        int cand = (lo2(a) == target) ? 2 * p
                 : ((hi2(a) == target) ? 2 * p + 1 : NSAM);
        found = min(found, cand);
    }
    return found;
}

__global__ void __launch_bounds__(THREADS, 2)
gq_kernel(const float* __restrict__ z,
          const float* __restrict__ eps,
          const float* __restrict__ prior,
          float* __restrict__ out,
          int out_size)
{
    // Packed sample table: per pair p (= samples 2p, 2p+1), 4 f32x2 words:
    //   [S_g0 | S_g1 | S_g2 | S_g3]
    // All other terms folded into per-query coefficients:
    //   u_g = mu*e^{-lv},  vh_g = 0.5*(1 - e^{-lv})
    //   score ~ sum_g S*(u + vh*S)   (per-query/global constants dropped)
    __shared__ __align__(16) float tab[NPAIR * TSTRIDE];   // 16384 B per CTA

    const int tid = threadIdx.x;
    #pragma unroll
    for (int n = tid; n < NSAM; n += THREADS) {
        float4 s = reinterpret_cast<const float4*>(prior)[n];
        int p = n >> 1, h = n & 1;
        float* t = &tab[p * TSTRIDE];
        t[0 + h] = s.x;  t[2 + h] = s.y;  t[4 + h] = s.z;  t[6 + h] = s.w;
    }

    // Each thread owns 2 consecutive queries k0, k0+1. Grid is exact: no tail.
    const int gtid = blockIdx.x * THREADS + tid;
    const int k0   = gtid * QPT;
    const int bl = k0 >> 6;     // (b*L + l)
    const int j  = k0 & 63;

    // Packed per-query coefficients
    unsigned long long uu[QPT][4], vh[QPT][4];

    #pragma unroll
    for (int g = 0; g < 4; g++) {
        const int moff = bl * 512 + g * 64 + j;           // mu
        float2 mu2 = *reinterpret_cast<const float2*>(z + moff);
        float2 lv2 = *reinterpret_cast<const float2*>(z + moff + 256);
        lv2.x = fminf(fmaxf(lv2.x, -30.0f), 20.0f);
        lv2.y = fminf(fmaxf(lv2.y, -30.0f), 20.0f);
        float ivx = expf(-lv2.x), ivy = expf(-lv2.y);
        uu[0][g] = pack2(mu2.x * ivx);  vh[0][g] = pack2(0.5f * (1.0f - ivx));
        uu[1][g] = pack2(mu2.y * ivy);  vh[1][g] = pack2(0.5f * (1.0f - ivy));

        // Fused zhat_noquant = mu + eps * exp(0.5*logvar)
        const int eoff = bl * 256 + g * 64 + j;
        float2 e2 = *reinterpret_cast<const float2*>(eps + eoff);
        float2 nq;
        nq.x = fmaf(e2.x, expf(0.5f * lv2.x), mu2.x);
        nq.y = fmaf(e2.y, expf(0.5f * lv2.y), mu2.y);
        if (out_size >= IDX_OFF)
            *reinterpret_cast<float2*>(out + NOQ_OFF + eoff) = nq;
    }
    __syncthreads();

    const float NEG_INF = -__int_as_float(0x7f800000);
    // One running max per query; even/odd lane resolved in the rescan.
    float g0 = NEG_INF, g1 = NEG_INF;
    int   c0 = 0, c1 = 0;

    for (int ch = 0; ch < NCHUNK; ch++) {
        float m0 = NEG_INF, m1 = NEG_INF;
        const float* cbase = &tab[ch * CHUNK * TSTRIDE];
        #pragma unroll
        for (int t = 0; t < CHUNK; t++) {
            const float* base = cbase + t * TSTRIDE;
            ulonglong2 wa = *reinterpret_cast<const ulonglong2*>(base + 0);   // S0,S1
            ulonglong2 wb = *reinterpret_cast<const ulonglong2*>(base + 4);   // S2,S3

            // 2 independent score chains (one per query)
            unsigned long long t0, t1, a0, a1;
            t0 = ffma2(vh[0][0], wa.x, uu[0][0]);  t1 = ffma2(vh[1][0], wa.x, uu[1][0]);
            a0 = fmul2(wa.x, t0);                  a1 = fmul2(wa.x, t1);
            t0 = ffma2(vh[0][1], wa.y, uu[0][1]);  t1 = ffma2(vh[1][1], wa.y, uu[1][1]);
            a0 = ffma2(wa.y, t0, a0);              a1 = ffma2(wa.y, t1, a1);
            t0 = ffma2(vh[0][2], wb.x, uu[0][2]);  t1 = ffma2(vh[1][2], wb.x, uu[1][2]);
            a0 = ffma2(wb.x, t0, a0);              a1 = ffma2(wb.x, t1, a1);
            t0 = ffma2(vh[0][3], wb.y, uu[0][3]);  t1 = ffma2(vh[1][3], wb.y, uu[1][3]);
            a0 = ffma2(wb.y, t0, a0);              a1 = ffma2(wb.y, t1, a1);

            m0 = fmaxf(m0, fmaxf(lo2(a0), hi2(a0)));
            m1 = fmaxf(m1, fmaxf(lo2(a1), hi2(a1)));
        }
        // Strict '>' keeps the earliest chunk on ties (first-index semantics)
        if (m0 > g0) { g0 = m0; c0 = ch; }
        if (m1 > g1) { g1 = m1; c1 = ch; }
    }

    // Resolve exact indices by rescanning each query's winning chunk
    int bidx0 = rescan_chunk(tab, uu[0], vh[0], c0, g0);
    int bidx1 = rescan_chunk(tab, uu[1], vh[1], c1, g1);

    {
        // Gather winning prior rows (prior table is L2-hot, 16 KB)
        float4 s0 = reinterpret_cast<const float4*>(prior)[bidx0];
        float4 s1 = reinterpret_cast<const float4*>(prior)[bidx1];
        const int obase = bl * 256 + j;
        *reinterpret_cast<float2*>(out + ZHAT_OFF + obase +   0) = make_float2(s0.x, s1.x);
        *reinterpret_cast<float2*>(out + ZHAT_OFF + obase +  64) = make_float2(s0.y, s1.y);
        *reinterpret_cast<float2*>(out + ZHAT_OFF + obase + 128) = make_float2(s0.z, s1.z);
        *reinterpret_cast<float2*>(out + ZHAT_OFF + obase + 192) = make_float2(s0.w, s1.w);
        if (out_size >= FULL_OUT) {
            *reinterpret_cast<float2*>(out + IDX_OFF + k0) =
                make_float2((float)bidx0, (float)bidx1);
        }
    }
}

extern "C" void kernel_launch(void* const* d_in, const int* in_sizes, int n_in,
                              void* d_out, int out_size) {
    const float* z     = (const float*)d_in[0];
    const float* eps   = (const float*)d_in[1];
    const float* prior = (const float*)d_in[2];
    (void)in_sizes; (void)n_in;
    const int thread_slots = NQ / QPT;           // 131072
    const int blocks = thread_slots / THREADS;   // 256 exactly -> no tail
    gq_kernel<<<blocks, THREADS>>>(z, eps, prior, (float*)d_out, out_size);
}

// round 7
// speedup vs baseline: 1.1664x; 1.1664x over previous
#include <cuda_runtime.h>
#include <math.h>

// Problem constants (fixed shapes from reference)
#define NQ      262144      // total queries = B*L*cg = 4*1024*64
#define NSAM    1024        // prior samples
#define NPAIR   512         // sample pairs (f32x2 packing)
#define TSTRIDE 8           // floats per pair row in smem table (32 B rows: S only)
#define THREADS 448
#define QPT     4           // queries per thread
#define CHUNK   16          // pairs per argmax chunk
#define NCHUNK  (NPAIR / CHUNK)
#define ZHAT_OFF   0
#define NOQ_OFF    1048576  // B*L*C
#define IDX_OFF    2097152  // 2*B*L*C
#define FULL_OUT   2359296  // + B*L*cg

// ---- packed f32x2 helpers (Blackwell FFMA2/FMUL2) ----
__device__ __forceinline__ unsigned long long ffma2(unsigned long long a,
                                                    unsigned long long b,
                                                    unsigned long long c) {
    unsigned long long d;
    asm("fma.rn.f32x2 %0, %1, %2, %3;" : "=l"(d) : "l"(a), "l"(b), "l"(c));
    return d;
}
__device__ __forceinline__ unsigned long long fmul2(unsigned long long a,
                                                    unsigned long long b) {
    unsigned long long d;
    asm("mul.rn.f32x2 %0, %1, %2;" : "=l"(d) : "l"(a), "l"(b));
    return d;
}
__device__ __forceinline__ unsigned long long pack2(float x) {
    unsigned long long r;
    asm("mov.b64 %0, {%1, %1};" : "=l"(r) : "f"(x));
    return r;
}
__device__ __forceinline__ float lo2(unsigned long long a) {
    return __uint_as_float((unsigned)(a & 0xffffffffull));
}
__device__ __forceinline__ float hi2(unsigned long long a) {
    return __uint_as_float((unsigned)(a >> 32));
}

// Factored score for one query against one sample pair:
//   acc = sum_g S_g * (u_g + vh_g * S_g)
// Both main loop and rescan use this exact sequence -> bit-identical results.
__device__ __forceinline__ unsigned long long score_pair(
        const unsigned long long* uu, const unsigned long long* vh,
        unsigned long long s0, unsigned long long s1,
        unsigned long long s2, unsigned long long s3) {
    unsigned long long t, a;
    t = ffma2(vh[0], s0, uu[0]);  a = fmul2(s0, t);
    t = ffma2(vh[1], s1, uu[1]);  a = ffma2(s1, t, a);
    t = ffma2(vh[2], s2, uu[2]);  a = ffma2(s2, t, a);
    t = ffma2(vh[3], s3, uu[3]);  a = ffma2(s3, t, a);
    return a;
}

// Recompute one chunk's scores for one query/stream; return first pair index
// whose selected lane equals target exactly (bit-deterministic recompute).
__device__ __forceinline__ int rescan_chunk(const float* __restrict__ tab,
                                            const unsigned long long* uu,
                                            const unsigned long long* vh,
                                            int chunk, float target, int odd) {
    int found = NPAIR;    // min-reduce => first match
    #pragma unroll 4
    for (int t = 0; t < CHUNK; t++) {
        int p = chunk * CHUNK + t;
        const float* base = &tab[p * TSTRIDE];
        ulonglong2 wa = *reinterpret_cast<const ulonglong2*>(base + 0);   // S0,S1
        ulonglong2 wb = *reinterpret_cast<const ulonglong2*>(base + 4);   // S2,S3
        unsigned long long a = score_pair(uu, vh, wa.x, wa.y, wb.x, wb.y);
        float v = odd ? hi2(a) : lo2(a);
        if (v == target) found = min(found, p);
    }
    return found;
}

__global__ void __launch_bounds__(THREADS, 1)
gq_kernel(const float* __restrict__ z,
          const float* __restrict__ eps,
          const float* __restrict__ prior,
          float* __restrict__ out,
          int out_size)
{
    // Packed sample table: per pair p (= samples 2p, 2p+1), 4 f32x2 words:
    //   [S_g0 | S_g1 | S_g2 | S_g3]
    // All other terms folded into per-query coefficients:
    //   u_g = mu*e^{-lv},  vh_g = 0.5*(1 - e^{-lv})
    //   score ~ sum_g S*(u + vh*S)   (per-query/global constants dropped)
    __shared__ __align__(16) float tab[NPAIR * TSTRIDE];   // 16384 B per CTA

    const int tid = threadIdx.x;
    for (int n = tid; n < NSAM; n += THREADS) {
        float4 s = reinterpret_cast<const float4*>(prior)[n];
        int p = n >> 1, h = n & 1;
        float* t = &tab[p * TSTRIDE];
        t[0 + h] = s.x;  t[2 + h] = s.y;  t[4 + h] = s.z;  t[6 + h] = s.w;
    }

    // Each thread owns 4 consecutive queries k0..k0+3 (j%4==0, never crosses a row)
    const int gtid = blockIdx.x * THREADS + tid;
    const int k0   = gtid * QPT;
    const bool valid = (k0 < NQ);
    const int bl = k0 >> 6;     // (b*L + l)
    const int j  = k0 & 63;

    // Packed per-query coefficients
    unsigned long long uu[QPT][4], vh[QPT][4];

    if (valid) {
        #pragma unroll
        for (int g = 0; g < 4; g++) {
            const int moff = bl * 512 + g * 64 + j;           // mu
            float4 mu4 = *reinterpret_cast<const float4*>(z + moff);
            float4 lv4 = *reinterpret_cast<const float4*>(z + moff + 256);
            lv4.x = fminf(fmaxf(lv4.x, -30.0f), 20.0f);
            lv4.y = fminf(fmaxf(lv4.y, -30.0f), 20.0f);
            lv4.z = fminf(fmaxf(lv4.z, -30.0f), 20.0f);
            lv4.w = fminf(fmaxf(lv4.w, -30.0f), 20.0f);
            float ivx = expf(-lv4.x), ivy = expf(-lv4.y);
            float ivz = expf(-lv4.z), ivw = expf(-lv4.w);
            uu[0][g] = pack2(mu4.x * ivx);  vh[0][g] = pack2(0.5f * (1.0f - ivx));
            uu[1][g] = pack2(mu4.y * ivy);  vh[1][g] = pack2(0.5f * (1.0f - ivy));
            uu[2][g] = pack2(mu4.z * ivz);  vh[2][g] = pack2(0.5f * (1.0f - ivz));
            uu[3][g] = pack2(mu4.w * ivw);  vh[3][g] = pack2(0.5f * (1.0f - ivw));

            // Fused zhat_noquant = mu + eps * exp(0.5*logvar)
            const int eoff = bl * 256 + g * 64 + j;
            float4 e4 = *reinterpret_cast<const float4*>(eps + eoff);
            float4 nq;
            nq.x = fmaf(e4.x, expf(0.5f * lv4.x), mu4.x);
            nq.y = fmaf(e4.y, expf(0.5f * lv4.y), mu4.y);
            nq.z = fmaf(e4.z, expf(0.5f * lv4.z), mu4.z);
            nq.w = fmaf(e4.w, expf(0.5f * lv4.w), mu4.w);
            if (out_size >= IDX_OFF)
                *reinterpret_cast<float4*>(out + NOQ_OFF + eoff) = nq;
        }
    }
    __syncthreads();
    if (!valid) return;   // tail threads exit (no further barriers)

    const float NEG_INF = -__int_as_float(0x7f800000);
    // Per-query, per-stream (even/odd lane) chunk argmax state
    float ge[QPT], go[QPT];
    int   ce[QPT], co[QPT];
    #pragma unroll
    for (int q = 0; q < QPT; q++) { ge[q] = NEG_INF; go[q] = NEG_INF; ce[q] = 0; co[q] = 0; }

    for (int ch = 0; ch < NCHUNK; ch++) {
        float me[QPT], mo[QPT];
        #pragma unroll
        for (int q = 0; q < QPT; q++) { me[q] = NEG_INF; mo[q] = NEG_INF; }

        const float* cbase = &tab[ch * CHUNK * TSTRIDE];
        #pragma unroll
        for (int t = 0; t < CHUNK; t++) {
            const float* base = cbase + t * TSTRIDE;
            ulonglong2 wa = *reinterpret_cast<const ulonglong2*>(base + 0);   // S0,S1
            ulonglong2 wb = *reinterpret_cast<const ulonglong2*>(base + 4);   // S2,S3

            #pragma unroll
            for (int q = 0; q < QPT; q++) {
                unsigned long long a = score_pair(uu[q], vh[q], wa.x, wa.y, wb.x, wb.y);
                me[q] = fmaxf(me[q], lo2(a));
                mo[q] = fmaxf(mo[q], hi2(a));
            }
        }
        // Strict '>' keeps the earliest chunk on ties (first-index semantics)
        #pragma unroll
        for (int q = 0; q < QPT; q++) {
            if (me[q] > ge[q]) { ge[q] = me[q]; ce[q] = ch; }
            if (mo[q] > go[q]) { go[q] = mo[q]; co[q] = ch; }
        }
    }

    // Resolve exact indices by rescanning the winning chunk(s)
    int bidx[QPT];
    #pragma unroll
    for (int q = 0; q < QPT; q++) {
        if (go[q] > ge[q]) {
            bidx[q] = 2 * rescan_chunk(tab, uu[q], vh[q], co[q], go[q], 1) + 1;
        } else if (ge[q] > go[q]) {
            bidx[q] = 2 * rescan_chunk(tab, uu[q], vh[q], ce[q], ge[q], 0);
        } else {
            int pe = rescan_chunk(tab, uu[q], vh[q], ce[q], ge[q], 0);
            int po = rescan_chunk(tab, uu[q], vh[q], co[q], go[q], 1);
            bidx[q] = min(2 * pe, 2 * po + 1);   // exact tie: first sample index
        }
    }

    {
        // Gather winning prior rows (prior table is L2-hot, 16 KB)
        float r[QPT][4];
        #pragma unroll
        for (int q = 0; q < QPT; q++) {
            float4 s = reinterpret_cast<const float4*>(prior)[bidx[q]];
            r[q][0] = s.x; r[q][1] = s.y; r[q][2] = s.z; r[q][3] = s.w;
        }
        const int obase = bl * 256 + j;
        #pragma unroll
        for (int g = 0; g < 4; g++) {
            float4 o4 = make_float4(r[0][g], r[1][g], r[2][g], r[3][g]);
            *reinterpret_cast<float4*>(out + ZHAT_OFF + obase + g * 64) = o4;
        }
        if (out_size >= FULL_OUT) {
            float4 i4 = make_float4((float)bidx[0], (float)bidx[1],
                                    (float)bidx[2], (float)bidx[3]);
            *reinterpret_cast<float4*>(out + IDX_OFF + k0) = i4;
        }
    }
}

extern "C" void kernel_launch(void* const* d_in, const int* in_sizes, int n_in,
                              void* d_out, int out_size) {
    const float* z     = (const float*)d_in[0];
    const float* eps   = (const float*)d_in[1];
    const float* prior = (const float*)d_in[2];
    (void)in_sizes; (void)n_in;
    const int thread_slots = NQ / QPT;                         // 65536
    const int blocks = (thread_slots + THREADS - 1) / THREADS; // 147 -> 1 CTA/SM, one wave
    gq_kernel<<<blocks, THREADS>>>(z, eps, prior, (float*)d_out, out_size);
}

// round 8
// speedup vs baseline: 1.2780x; 1.0957x over previous
#include <cuda_runtime.h>
#include <math.h>

// Problem constants (fixed shapes from reference)
#define NQ      262144      // total queries = B*L*cg = 4*1024*64
#define NSAM    1024        // prior samples
#define THREADS 448
#define QPT     4           // queries per thread (2 f32x2 lane-packs)
#define CHUNK   16          // samples per argmax chunk
#define NCHUNK  (NSAM / CHUNK)
#define ZHAT_OFF   0
#define NOQ_OFF    1048576  // B*L*C
#define IDX_OFF    2097152  // 2*B*L*C
#define FULL_OUT   2359296  // + B*L*cg

// ---- packed f32x2 helpers (Blackwell FFMA2/FMUL2) ----
__device__ __forceinline__ unsigned long long ffma2(unsigned long long a,
                                                    unsigned long long b,
                                                    unsigned long long c) {
    unsigned long long d;
    asm("fma.rn.f32x2 %0, %1, %2, %3;" : "=l"(d) : "l"(a), "l"(b), "l"(c));
    return d;
}
__device__ __forceinline__ unsigned long long fmul2(unsigned long long a,
                                                    unsigned long long b) {
    unsigned long long d;
    asm("mul.rn.f32x2 %0, %1, %2;" : "=l"(d) : "l"(a), "l"(b));
    return d;
}
__device__ __forceinline__ unsigned long long pack2(float x) {     // (x, x)
    unsigned long long r;
    asm("mov.b64 %0, {%1, %1};" : "=l"(r) : "f"(x));
    return r;
}
__device__ __forceinline__ unsigned long long packxy(float lo, float hi) {  // (lo, hi)
    unsigned long long r;
    asm("mov.b64 %0, {%1, %2};" : "=l"(r) : "f"(lo), "f"(hi));
    return r;
}
__device__ __forceinline__ float lo2(unsigned long long a) {
    return __uint_as_float((unsigned)(a & 0xffffffffull));
}
__device__ __forceinline__ float hi2(unsigned long long a) {
    return __uint_as_float((unsigned)(a >> 32));
}

// Packed score of TWO queries (in lanes) against ONE sample:
//   lane: score = sum_g s_g * (u_g + vh_g * s_g)
// s_g arrives lane-duplicated. Main loop and rescan share this sequence
// -> bit-identical recompute.
__device__ __forceinline__ unsigned long long score2(
        const unsigned long long* u, const unsigned long long* vh,
        unsigned long long s0, unsigned long long s1,
        unsigned long long s2, unsigned long long s3) {
    unsigned long long t, a;
    t = ffma2(vh[0], s0, u[0]);  a = fmul2(s0, t);
    t = ffma2(vh[1], s1, u[1]);  a = ffma2(s1, t, a);
    t = ffma2(vh[2], s2, u[2]);  a = ffma2(s2, t, a);
    t = ffma2(vh[3], s3, u[3]);  a = ffma2(s3, t, a);
    return a;
}

// Recompute one chunk for one lane-pack; return smallest sample index whose
// selected lane equals target exactly.
__device__ __forceinline__ int rescan_chunk(const float4* __restrict__ tab,
                                            const unsigned long long* u,
                                            const unsigned long long* vh,
                                            int chunk, float target, int odd) {
    int found = NSAM;
    #pragma unroll 4
    for (int t = 0; t < CHUNK; t++) {
        int n = chunk * CHUNK + t;
        float4 s = tab[n];
        unsigned long long a = score2(u, vh, pack2(s.x), pack2(s.y),
                                             pack2(s.z), pack2(s.w));
        float v = odd ? hi2(a) : lo2(a);
        if (v == target) found = min(found, n);
    }
    return found;
}

__global__ void __launch_bounds__(THREADS, 1)
gq_kernel(const float* __restrict__ z,
          const float* __restrict__ eps,
          const float* __restrict__ prior,
          float* __restrict__ out,
          int out_size)
{
    // Sample table = raw prior rows: tab[n] = (S_g0, S_g1, S_g2, S_g3)
    __shared__ __align__(16) float4 tab[NSAM];     // 16384 B

    const int tid = threadIdx.x;
    for (int n = tid; n < NSAM; n += THREADS)
        tab[n] = reinterpret_cast<const float4*>(prior)[n];

    // Each thread owns 4 consecutive queries k0..k0+3 (j%4==0, same row)
    const int gtid = blockIdx.x * THREADS + tid;
    const int k0   = gtid * QPT;
    const bool valid = (k0 < NQ);
    const int bl = k0 >> 6;     // (b*L + l)
    const int j  = k0 & 63;

    // Lane-packed per-query coefficients: u01[g]=(u_q0,u_q1), u23[g]=(u_q2,u_q3)
    unsigned long long u01[4], u23[4], vh01[4], vh23[4];

    if (valid) {
        #pragma unroll
        for (int g = 0; g < 4; g++) {
            const int moff = bl * 512 + g * 64 + j;           // mu
            float4 mu4 = *reinterpret_cast<const float4*>(z + moff);
            float4 lv4 = *reinterpret_cast<const float4*>(z + moff + 256);
            lv4.x = fminf(fmaxf(lv4.x, -30.0f), 20.0f);
            lv4.y = fminf(fmaxf(lv4.y, -30.0f), 20.0f);
            lv4.z = fminf(fmaxf(lv4.z, -30.0f), 20.0f);
            lv4.w = fminf(fmaxf(lv4.w, -30.0f), 20.0f);
            float ivx = expf(-lv4.x), ivy = expf(-lv4.y);
            float ivz = expf(-lv4.z), ivw = expf(-lv4.w);
            u01[g]  = packxy(mu4.x * ivx, mu4.y * ivy);
            u23[g]  = packxy(mu4.z * ivz, mu4.w * ivw);
            vh01[g] = packxy(0.5f * (1.0f - ivx), 0.5f * (1.0f - ivy));
            vh23[g] = packxy(0.5f * (1.0f - ivz), 0.5f * (1.0f - ivw));

            // Fused zhat_noquant = mu + eps * exp(0.5*logvar)
            const int eoff = bl * 256 + g * 64 + j;
            float4 e4 = *reinterpret_cast<const float4*>(eps + eoff);
            float4 nq;
            nq.x = fmaf(e4.x, expf(0.5f * lv4.x), mu4.x);
            nq.y = fmaf(e4.y, expf(0.5f * lv4.y), mu4.y);
            nq.z = fmaf(e4.z, expf(0.5f * lv4.z), mu4.z);
            nq.w = fmaf(e4.w, expf(0.5f * lv4.w), mu4.w);
            if (out_size >= IDX_OFF)
                *reinterpret_cast<float4*>(out + NOQ_OFF + eoff) = nq;
        }
    }
    __syncthreads();
    if (!valid) return;   // tail threads exit (no further barriers)

    const float NEG_INF = -__int_as_float(0x7f800000);
    float gm[QPT];
    int   gc[QPT];
    #pragma unroll
    for (int q = 0; q < QPT; q++) { gm[q] = NEG_INF; gc[q] = 0; }

    for (int ch = 0; ch < NCHUNK; ch++) {
        float m0 = NEG_INF, m1 = NEG_INF, m2 = NEG_INF, m3 = NEG_INF;
        const float4* cbase = &tab[ch * CHUNK];
        #pragma unroll
        for (int t = 0; t < CHUNK; t++) {
            float4 s = cbase[t];                       // one LDS.128 per sample
            unsigned long long s0 = pack2(s.x), s1 = pack2(s.y);
            unsigned long long s2 = pack2(s.z), s3 = pack2(s.w);
            unsigned long long a01 = score2(u01, vh01, s0, s1, s2, s3);
            unsigned long long a23 = score2(u23, vh23, s0, s1, s2, s3);
            m0 = fmaxf(m0, lo2(a01));
            m1 = fmaxf(m1, hi2(a01));
            m2 = fmaxf(m2, lo2(a23));
            m3 = fmaxf(m3, hi2(a23));
        }
        // Strict '>' keeps the earliest chunk on ties (first-index semantics)
        if (m0 > gm[0]) { gm[0] = m0; gc[0] = ch; }
        if (m1 > gm[1]) { gm[1] = m1; gc[1] = ch; }
        if (m2 > gm[2]) { gm[2] = m2; gc[2] = ch; }
        if (m3 > gm[3]) { gm[3] = m3; gc[3] = ch; }
    }

    // Resolve exact indices by rescanning each query's winning chunk
    int bidx[QPT];
    bidx[0] = rescan_chunk(tab, u01, vh01, gc[0], gm[0], 0);
    bidx[1] = rescan_chunk(tab, u01, vh01, gc[1], gm[1], 1);
    bidx[2] = rescan_chunk(tab, u23, vh23, gc[2], gm[2], 0);
    bidx[3] = rescan_chunk(tab, u23, vh23, gc[3], gm[3], 1);

    {
        // Gather winning prior rows from the smem table
        float r[QPT][4];
        #pragma unroll
        for (int q = 0; q < QPT; q++) {
            float4 s = tab[bidx[q]];
            r[q][0] = s.x; r[q][1] = s.y; r[q][2] = s.z; r[q][3] = s.w;
        }
        const int obase = bl * 256 + j;
        #pragma unroll
        for (int g = 0; g < 4; g++) {
            float4 o4 = make_float4(r[0][g], r[1][g], r[2][g], r[3][g]);
            *reinterpret_cast<float4*>(out + ZHAT_OFF + obase + g * 64) = o4;
        }
        if (out_size >= FULL_OUT) {
            float4 i4 = make_float4((float)bidx[0], (float)bidx[1],
                                    (float)bidx[2], (float)bidx[3]);
            *reinterpret_cast<float4*>(out + IDX_OFF + k0) = i4;
        }
    }
}

extern "C" void kernel_launch(void* const* d_in, const int* in_sizes, int n_in,
                              void* d_out, int out_size) {
    const float* z     = (const float*)d_in[0];
    const float* eps   = (const float*)d_in[1];
    const float* prior = (const float*)d_in[2];
    (void)in_sizes; (void)n_in;
    const int thread_slots = NQ / QPT;                         // 65536
    const int blocks = (thread_slots + THREADS - 1) / THREADS; // 147 -> one wave
    gq_kernel<<<blocks, THREADS>>>(z, eps, prior, (float*)d_out, out_size);
}

// round 9
// speedup vs baseline: 1.3850x; 1.0837x over previous
#include <cuda_runtime.h>
#include <math.h>

// Problem constants (fixed shapes from reference)
#define NQ      262144      // total queries = B*L*cg = 4*1024*64
#define NSAM    1024        // prior samples
#define THREADS 448
#define QPT     4           // queries per thread-PAIR (2 f32x2 lane-packs)
#define SPLIT   2           // threads per query-quad (each scans NSAM/SPLIT samples)
#define CHUNK   16          // samples per argmax chunk
#define NCHUNK  (NSAM / CHUNK)          // 64 total
#define CH_PER_THREAD (NCHUNK / SPLIT)  // 32 per thread
#define ZHAT_OFF   0
#define NOQ_OFF    1048576  // B*L*C
#define IDX_OFF    2097152  // 2*B*L*C
#define FULL_OUT   2359296  // + B*L*cg

// ---- packed f32x2 helpers (Blackwell FFMA2/FMUL2) ----
__device__ __forceinline__ unsigned long long ffma2(unsigned long long a,
                                                    unsigned long long b,
                                                    unsigned long long c) {
    unsigned long long d;
    asm("fma.rn.f32x2 %0, %1, %2, %3;" : "=l"(d) : "l"(a), "l"(b), "l"(c));
    return d;
}
__device__ __forceinline__ unsigned long long fmul2(unsigned long long a,
                                                    unsigned long long b) {
    unsigned long long d;
    asm("mul.rn.f32x2 %0, %1, %2;" : "=l"(d) : "l"(a), "l"(b));
    return d;
}
__device__ __forceinline__ unsigned long long pack2(float x) {     // (x, x)
    unsigned long long r;
    asm("mov.b64 %0, {%1, %1};" : "=l"(r) : "f"(x));
    return r;
}
__device__ __forceinline__ unsigned long long packxy(float lo, float hi) {  // (lo, hi)
    unsigned long long r;
    asm("mov.b64 %0, {%1, %2};" : "=l"(r) : "f"(lo), "f"(hi));
    return r;
}
__device__ __forceinline__ float lo2(unsigned long long a) {
    return __uint_as_float((unsigned)(a & 0xffffffffull));
}
__device__ __forceinline__ float hi2(unsigned long long a) {
    return __uint_as_float((unsigned)(a >> 32));
}

// Packed score of TWO queries (in lanes) against ONE sample.
// Main loop and rescan share this sequence -> bit-identical recompute.
__device__ __forceinline__ unsigned long long score2(
        const unsigned long long* u, const unsigned long long* vh,
        unsigned long long s0, unsigned long long s1,
        unsigned long long s2, unsigned long long s3) {
    unsigned long long t, a;
    t = ffma2(vh[0], s0, u[0]);  a = fmul2(s0, t);
    t = ffma2(vh[1], s1, u[1]);  a = ffma2(s1, t, a);
    t = ffma2(vh[2], s2, u[2]);  a = ffma2(s2, t, a);
    t = ffma2(vh[3], s3, u[3]);  a = ffma2(s3, t, a);
    return a;
}

// Recompute one chunk for one lane-pack; return smallest sample index whose
// selected lane equals target exactly.
__device__ __forceinline__ int rescan_chunk(const float4* __restrict__ tab,
                                            const unsigned long long* u,
                                            const unsigned long long* vh,
                                            int chunk, float target, int odd) {
    int found = NSAM;
    #pragma unroll 4
    for (int t = 0; t < CHUNK; t++) {
        int n = chunk * CHUNK + t;
        float4 s = tab[n];
        unsigned long long a = score2(u, vh, pack2(s.x), pack2(s.y),
                                             pack2(s.z), pack2(s.w));
        float v = odd ? hi2(a) : lo2(a);
        if (v == target) found = min(found, n);
    }
    return found;
}

__global__ void __launch_bounds__(THREADS, 2)
gq_kernel(const float* __restrict__ z,
          const float* __restrict__ eps,
          const float* __restrict__ prior,
          float* __restrict__ out,
          int out_size)
{
    // Sample table = raw prior rows: tab[n] = (S_g0, S_g1, S_g2, S_g3)
    __shared__ __align__(16) float4 tab[NSAM];     // 16384 B

    const int tid = threadIdx.x;
    for (int n = tid; n < NSAM; n += THREADS)
        tab[n] = reinterpret_cast<const float4*>(prior)[n];

    // Adjacent thread pair (2i, 2i+1) owns query-quad i; h = which sample half.
    const int gtid   = blockIdx.x * THREADS + tid;
    const int pairid = gtid >> 1;
    const int h      = gtid & 1;
    const int k0     = pairid * QPT;
    const bool valid = (k0 < NQ);
    const int bl = k0 >> 6;     // (b*L + l)
    const int j  = k0 & 63;

    // Lane-packed per-query coefficients: u01[g]=(u_q0,u_q1), u23[g]=(u_q2,u_q3)
    unsigned long long u01[4], u23[4], vh01[4], vh23[4];

    if (valid) {
        #pragma unroll
        for (int g = 0; g < 4; g++) {
            const int moff = bl * 512 + g * 64 + j;           // mu
            float4 mu4 = *reinterpret_cast<const float4*>(z + moff);
            float4 lv4 = *reinterpret_cast<const float4*>(z + moff + 256);
            lv4.x = fminf(fmaxf(lv4.x, -30.0f), 20.0f);
            lv4.y = fminf(fmaxf(lv4.y, -30.0f), 20.0f);
            lv4.z = fminf(fmaxf(lv4.z, -30.0f), 20.0f);
            lv4.w = fminf(fmaxf(lv4.w, -30.0f), 20.0f);
            float ivx = expf(-lv4.x), ivy = expf(-lv4.y);
            float ivz = expf(-lv4.z), ivw = expf(-lv4.w);
            u01[g]  = packxy(mu4.x * ivx, mu4.y * ivy);
            u23[g]  = packxy(mu4.z * ivz, mu4.w * ivw);
            vh01[g] = packxy(0.5f * (1.0f - ivx), 0.5f * (1.0f - ivy));
            vh23[g] = packxy(0.5f * (1.0f - ivz), 0.5f * (1.0f - ivw));

            // Fused zhat_noquant (written once per quad, by the h==0 thread)
            if (h == 0) {
                const int eoff = bl * 256 + g * 64 + j;
                float4 e4 = *reinterpret_cast<const float4*>(eps + eoff);
                float4 nq;
                nq.x = fmaf(e4.x, expf(0.5f * lv4.x), mu4.x);
                nq.y = fmaf(e4.y, expf(0.5f * lv4.y), mu4.y);
                nq.z = fmaf(e4.z, expf(0.5f * lv4.z), mu4.z);
                nq.w = fmaf(e4.w, expf(0.5f * lv4.w), mu4.w);
                if (out_size >= IDX_OFF)
                    *reinterpret_cast<float4*>(out + NOQ_OFF + eoff) = nq;
            }
        }
    }
    __syncthreads();
    if (!valid) return;   // whole warps exit (pairs adjacent); shuffles below safe

    const float NEG_INF = -__int_as_float(0x7f800000);
    float gm[QPT];
    int   gc[QPT];
    #pragma unroll
    for (int q = 0; q < QPT; q++) { gm[q] = NEG_INF; gc[q] = 0; }

    // This thread scans chunks [h*32, h*32+32) = samples [h*512, h*512+512)
    const int ch0 = h * CH_PER_THREAD;
    for (int ci = 0; ci < CH_PER_THREAD; ci++) {
        const int ch = ch0 + ci;
        float m0 = NEG_INF, m1 = NEG_INF, m2 = NEG_INF, m3 = NEG_INF;
        const float4* cbase = &tab[ch * CHUNK];
        #pragma unroll
        for (int t = 0; t < CHUNK; t++) {
            float4 s = cbase[t];                       // one LDS.128 per sample
            unsigned long long s0 = pack2(s.x), s1 = pack2(s.y);
            unsigned long long s2 = pack2(s.z), s3 = pack2(s.w);
            unsigned long long a01 = score2(u01, vh01, s0, s1, s2, s3);
            unsigned long long a23 = score2(u23, vh23, s0, s1, s2, s3);
            m0 = fmaxf(m0, lo2(a01));
            m1 = fmaxf(m1, hi2(a01));
            m2 = fmaxf(m2, lo2(a23));
            m3 = fmaxf(m3, hi2(a23));
        }
        // Strict '>' keeps the earliest chunk on ties (first-index semantics)
        if (m0 > gm[0]) { gm[0] = m0; gc[0] = ch; }
        if (m1 > gm[1]) { gm[1] = m1; gc[1] = ch; }
        if (m2 > gm[2]) { gm[2] = m2; gc[2] = ch; }
        if (m3 > gm[3]) { gm[3] = m3; gc[3] = ch; }
    }

    // Merge the two halves across the thread pair (xor-1 shuffle).
    // On equal max, smaller chunk id wins -> global first-index semantics.
    #pragma unroll
    for (int q = 0; q < QPT; q++) {
        float pm = __shfl_xor_sync(0xFFFFFFFFu, gm[q], 1);
        int   pc = __shfl_xor_sync(0xFFFFFFFFu, gc[q], 1);
        if (pm > gm[q] || (pm == gm[q] && pc < gc[q])) { gm[q] = pm; gc[q] = pc; }
    }

    if (h != 0) return;   // odd thread done; even thread resolves + writes

    // Resolve exact indices by rescanning each query's winning chunk
    int bidx[QPT];
    bidx[0] = rescan_chunk(tab, u01, vh01, gc[0], gm[0], 0);
    bidx[1] = rescan_chunk(tab, u01, vh01, gc[1], gm[1], 1);
    bidx[2] = rescan_chunk(tab, u23, vh23, gc[2], gm[2], 0);
    bidx[3] = rescan_chunk(tab, u23, vh23, gc[3], gm[3], 1);

    {
        // Gather winning prior rows from the smem table
        float r[QPT][4];
        #pragma unroll
        for (int q = 0; q < QPT; q++) {
            float4 s = tab[bidx[q]];
            r[q][0] = s.x; r[q][1] = s.y; r[q][2] = s.z; r[q][3] = s.w;
        }
        const int obase = bl * 256 + j;
        #pragma unroll
        for (int g = 0; g < 4; g++) {
            float4 o4 = make_float4(r[0][g], r[1][g], r[2][g], r[3][g]);
            *reinterpret_cast<float4*>(out + ZHAT_OFF + obase + g * 64) = o4;
        }
        if (out_size >= FULL_OUT) {
            float4 i4 = make_float4((float)bidx[0], (float)bidx[1],
                                    (float)bidx[2], (float)bidx[3]);
            *reinterpret_cast<float4*>(out + IDX_OFF + k0) = i4;
        }
    }
}

extern "C" void kernel_launch(void* const* d_in, const int* in_sizes, int n_in,
                              void* d_out, int out_size) {
    const float* z     = (const float*)d_in[0];
    const float* eps   = (const float*)d_in[1];
    const float* prior = (const float*)d_in[2];
    (void)in_sizes; (void)n_in;
    const int thread_slots = (NQ / QPT) * SPLIT;               // 131072
    const int blocks = (thread_slots + THREADS - 1) / THREADS; // 293 -> 2 CTAs/SM
    gq_kernel<<<blocks, THREADS>>>(z, eps, prior, (float*)d_out, out_size);
}